// round 7
// baseline (speedup 1.0000x reference)
#include <cuda_runtime.h>
#include <cstdint>

typedef unsigned long long ull;

// ---------- packed f32x2 helpers (sm_103a) ----------
__device__ __forceinline__ ull pack2(float a, float b) {
    ull r; asm("mov.b64 %0, {%1, %2};" : "=l"(r) : "f"(a), "f"(b)); return r;
}
__device__ __forceinline__ void unpack2(ull v, float& a, float& b) {
    asm("mov.b64 {%0, %1}, %2;" : "=f"(a), "=f"(b) : "l"(v));
}
__device__ __forceinline__ ull ffma2(ull a, ull b, ull c) {
    ull d; asm("fma.rn.f32x2 %0, %1, %2, %3;" : "=l"(d) : "l"(a), "l"(b), "l"(c)); return d;
}
__device__ __forceinline__ ull relu2(ull v) {
    float a, b; unpack2(v, a, b);
    return pack2(fmaxf(a, 0.f), fmaxf(b, 0.f));
}

#define NJ 24
#define JW 104          // ull per joint: 13 rows x 8 (7 dup weights + dup bias)
#define WPB 8           // warps per block
#define TPAD 26         // tile row stride in floats (even, conflict-free, >=25 for x stage)
#define TILE_FLOATS (128 * TPAD)                // 13312 B
#define XS_ULL (24 * 64)                        // packed-x per warp: 12288 B
#define SW_BYTES (NJ * JW * 8)                  // 19968
#define SMEM_BYTES (SW_BYTES + WPB * (XS_ULL * 8 + TILE_FLOATS * 4))  // 224768

// ---- joint forward for BOTH packs, sharing weight registers ----
__device__ __forceinline__ void joint_fwd2(const ull* wp, ull xp0, ull xp1,
                                           const ull* pf0, const ull* pf1,
                                           ull* fo0, ull* fo1) {
    ull h0[7], h1[7];
#pragma unroll
    for (int o = 0; o < 7; ++o) {
        const ulonglong2* r = reinterpret_cast<const ulonglong2*>(wp + o * 8);
        ulonglong2 q0 = r[0], q1 = r[1], q2 = r[2], q3 = r[3];
        ull a0 = ffma2(q0.x, xp0, q3.y);
        ull a1 = ffma2(q0.x, xp1, q3.y);
        a0 = ffma2(q0.y, pf0[0], a0);  a1 = ffma2(q0.y, pf1[0], a1);
        a0 = ffma2(q1.x, pf0[1], a0);  a1 = ffma2(q1.x, pf1[1], a1);
        a0 = ffma2(q1.y, pf0[2], a0);  a1 = ffma2(q1.y, pf1[2], a1);
        a0 = ffma2(q2.x, pf0[3], a0);  a1 = ffma2(q2.x, pf1[3], a1);
        a0 = ffma2(q2.y, pf0[4], a0);  a1 = ffma2(q2.y, pf1[4], a1);
        a0 = ffma2(q3.x, pf0[5], a0);  a1 = ffma2(q3.x, pf1[5], a1);
        h0[o] = relu2(a0);  h1[o] = relu2(a1);
    }
#pragma unroll
    for (int o = 0; o < 6; ++o) {
        const ulonglong2* r = reinterpret_cast<const ulonglong2*>(wp + 56 + o * 8);
        ulonglong2 q0 = r[0], q1 = r[1], q2 = r[2], q3 = r[3];
        ull a0 = ffma2(q0.x, h0[0], q3.y);
        ull a1 = ffma2(q0.x, h1[0], q3.y);
        a0 = ffma2(q0.y, h0[1], a0);  a1 = ffma2(q0.y, h1[1], a1);
        a0 = ffma2(q1.x, h0[2], a0);  a1 = ffma2(q1.x, h1[2], a1);
        a0 = ffma2(q1.y, h0[3], a0);  a1 = ffma2(q1.y, h1[3], a1);
        a0 = ffma2(q2.x, h0[4], a0);  a1 = ffma2(q2.x, h1[4], a1);
        a0 = ffma2(q2.y, h0[5], a0);  a1 = ffma2(q2.y, h1[5], a1);
        a0 = ffma2(q3.x, h0[6], a0);  a1 = ffma2(q3.x, h1[6], a1);
        fo0[o] = relu2(a0);  fo1[o] = relu2(a1);
    }
}

__device__ __forceinline__ void root_fwd2(const ull* wp, ull xp0, ull xp1,
                                          ull* fo0, ull* fo1) {
    ull h0[7], h1[7];
#pragma unroll
    for (int o = 0; o < 7; ++o) {
        ull w0 = wp[o * 8];
        ull bb = wp[o * 8 + 7];
        h0[o] = relu2(ffma2(w0, xp0, bb));
        h1[o] = relu2(ffma2(w0, xp1, bb));
    }
#pragma unroll
    for (int o = 0; o < 6; ++o) {
        const ulonglong2* r = reinterpret_cast<const ulonglong2*>(wp + 56 + o * 8);
        ulonglong2 q0 = r[0], q1 = r[1], q2 = r[2], q3 = r[3];
        ull a0 = ffma2(q0.x, h0[0], q3.y);
        ull a1 = ffma2(q0.x, h1[0], q3.y);
        a0 = ffma2(q0.y, h0[1], a0);  a1 = ffma2(q0.y, h1[1], a1);
        a0 = ffma2(q1.x, h0[2], a0);  a1 = ffma2(q1.x, h1[2], a1);
        a0 = ffma2(q1.y, h0[3], a0);  a1 = ffma2(q1.y, h1[3], a1);
        a0 = ffma2(q2.x, h0[4], a0);  a1 = ffma2(q2.x, h1[4], a1);
        a0 = ffma2(q2.y, h0[5], a0);  a1 = ffma2(q2.y, h1[5], a1);
        a0 = ffma2(q3.x, h0[6], a0);  a1 = ffma2(q3.x, h1[6], a1);
        fo0[o] = relu2(a0);  fo1[o] = relu2(a1);
    }
}

// store 6 packed values to two element rows (lows -> ra, highs -> rb)
__device__ __forceinline__ void store6(const ull* f, float* ra, float* rb, int cb) {
    float a0,b0,a1,b1,a2,b2,a3,b3,a4,b4,a5,b5;
    unpack2(f[0], a0, b0); unpack2(f[1], a1, b1); unpack2(f[2], a2, b2);
    unpack2(f[3], a3, b3); unpack2(f[4], a4, b4); unpack2(f[5], a5, b5);
    ((float2*)(ra + cb))[0] = make_float2(a0, a1);
    ((float2*)(ra + cb))[1] = make_float2(a2, a3);
    ((float2*)(ra + cb))[2] = make_float2(a4, a5);
    ((float2*)(rb + cb))[0] = make_float2(b0, b1);
    ((float2*)(rb + cb))[1] = make_float2(b2, b3);
    ((float2*)(rb + cb))[2] = make_float2(b4, b5);
}

__global__ void __launch_bounds__(WPB * 32)
StructureEncoder1D_kernel(const float* __restrict__ x,
                          const float* __restrict__ W1,
                          const float* __restrict__ b1,
                          const float* __restrict__ W2,
                          const float* __restrict__ b2,
                          float* __restrict__ out, int B) {
    extern __shared__ __align__(16) char dynsmem[];
    ull*   sw    = reinterpret_cast<ull*>(dynsmem);                  // dup weights
    ull*   xsall = reinterpret_cast<ull*>(dynsmem + SW_BYTES);       // packed x
    float* tiles = reinterpret_cast<float*>(dynsmem + SW_BYTES + WPB * XS_ULL * 8);

    // ---- cooperative weight fill: each ull = one weight duplicated ----
    for (int i = threadIdx.x; i < NJ * JW; i += blockDim.x) {
        int j = i / JW, r = i % JW, row = r >> 3, c = r & 7;
        float v;
        if (row < 7) {
            v = (c < 7) ? W1[j * 49 + row * 7 + c] : b1[j * 7 + row];
        } else {
            int rr = row - 7;
            v = (c < 7) ? W2[j * 42 + rr * 7 + c] : b2[j * 6 + rr];
        }
        ull u = (ull)__float_as_uint(v);
        sw[i] = u | (u << 32);
    }
    __syncthreads();

    const int lane   = threadIdx.x & 31;
    const int warpId = threadIdx.x >> 5;
    const int warpBase = (blockIdx.x * WPB + warpId) * 128;   // 128 elems per warp
    if (warpBase >= B) return;

    float* tile = tiles + warpId * TILE_FLOATS;
    ull*   xs   = xsall + warpId * XS_ULL;

    // ---- stage x: coalesced LDG.128 -> tile (row stride TPAD=26 floats) ----
    {
        const float4* xin = reinterpret_cast<const float4*>(x);
#pragma unroll
        for (int k = 0; k < 24; ++k) {
            int i = k * 32 + lane;               // [0,768): 128 rows x 6 float4
            int r = i / 6, c = i % 6;
            float4 v = make_float4(0.f, 0.f, 0.f, 0.f);
            if (warpBase + r < B) v = xin[(size_t)(warpBase + r) * 6 + c];
            float2* d = reinterpret_cast<float2*>(tile + r * TPAD + c * 4);
            d[0] = make_float2(v.x, v.y);
            d[1] = make_float2(v.z, v.w);
        }
    }
    __syncwarp();

    // ---- build packed-x: two packs per joint ----
#pragma unroll
    for (int j = 0; j < 24; ++j) {
        xs[j * 64 + lane] =
            pack2(tile[lane * TPAD + j],        tile[(lane + 32) * TPAD + j]);
        xs[j * 64 + 32 + lane] =
            pack2(tile[(lane + 64) * TPAD + j], tile[(lane + 96) * TPAD + j]);
    }
    __syncwarp();

    float* ta = tile + lane * TPAD;
    float* tb = tile + (lane + 32) * TPAD;
    float* tc = tile + (lane + 64) * TPAD;
    float* td = tile + (lane + 96) * TPAD;

    ull fA0[6], fA1[6], fB0[6], fB1[6], fC0[6], fC1[6];

#define X0(J) (xs[(J) * 64 + lane])
#define X1(J) (xs[(J) * 64 + 32 + lane])
#define WP(J) (sw + (J) * JW)
#define ST(F, CB) do { store6(F##0, ta, tb, CB); store6(F##1, tc, td, CB); } while (0)

    // flush eighth-tile: 128 rows x 18 cols -> out cols [H*18, H*18+18)
#define FLUSH(H) do {                                                          \
        __syncwarp();                                                          \
        _Pragma("unroll")                                                      \
        for (int k = 0; k < 36; ++k) {                                         \
            int i = k * 32 + lane;               /* [0,1152): 128 rows x 9 f2*/\
            int r = i / 9, c = i % 9;                                          \
            if (warpBase + r < B) {                                            \
                float2 v = *reinterpret_cast<const float2*>(                   \
                    tile + r * TPAD + c * 2);                                  \
                *reinterpret_cast<float2*>(                                    \
                    out + (size_t)(warpBase + r) * 144 + (H) * 18 + c * 2) = v;\
            }                                                                  \
        }                                                                      \
        __syncwarp();                                                          \
    } while (0)

    // ---- phase 0: joints {0,1,2} ----
    root_fwd2 (WP(0), X0(0), X1(0),            fA0, fA1); ST(fA, 0);
    joint_fwd2(WP(1), X0(1), X1(1), fA0, fA1,  fB0, fB1); ST(fB, 6);
    joint_fwd2(WP(2), X0(2), X1(2), fA0, fA1,  fC0, fC1); ST(fC, 12);
    FLUSH(0);
    // ---- phase 1: {3,4,5}  (fA=f0, fB=f1, fC=f2) ----
    joint_fwd2(WP(3), X0(3), X1(3), fA0, fA1,  fA0, fA1); ST(fA, 0);
    joint_fwd2(WP(4), X0(4), X1(4), fB0, fB1,  fB0, fB1); ST(fB, 6);
    joint_fwd2(WP(5), X0(5), X1(5), fC0, fC1,  fC0, fC1); ST(fC, 12);
    FLUSH(1);
    // ---- phase 2: {6,7,8}  (fA=f3, fB=f4, fC=f5) ----
    joint_fwd2(WP(6), X0(6), X1(6), fA0, fA1,  fA0, fA1); ST(fA, 0);
    joint_fwd2(WP(7), X0(7), X1(7), fB0, fB1,  fB0, fB1); ST(fB, 6);
    joint_fwd2(WP(8), X0(8), X1(8), fC0, fC1,  fC0, fC1); ST(fC, 12);
    FLUSH(2);
    // ---- phase 3: {9,10,11}  (fA=f6, fB=f7, fC=f8) ----
    joint_fwd2(WP(9),  X0(9),  X1(9),  fA0, fA1,  fA0, fA1); ST(fA, 0);
    joint_fwd2(WP(10), X0(10), X1(10), fB0, fB1,  fB0, fB1); ST(fB, 6);
    joint_fwd2(WP(11), X0(11), X1(11), fC0, fC1,  fC0, fC1); ST(fC, 12);
    FLUSH(3);
    // ---- phase 4: {12,13,14}  (fA=f9; parents of 12,13,14 are all 9) ----
    joint_fwd2(WP(12), X0(12), X1(12), fA0, fA1,  fB0, fB1); ST(fB, 0);
    joint_fwd2(WP(13), X0(13), X1(13), fA0, fA1,  fC0, fC1); ST(fC, 6);
    joint_fwd2(WP(14), X0(14), X1(14), fA0, fA1,  fA0, fA1); ST(fA, 12);
    FLUSH(4);
    // ---- phase 5: {15,16,17}  (fB=f12, fC=f13, fA=f14) ----
    joint_fwd2(WP(15), X0(15), X1(15), fB0, fB1,  fB0, fB1); ST(fB, 0);
    joint_fwd2(WP(16), X0(16), X1(16), fC0, fC1,  fC0, fC1); ST(fC, 6);
    joint_fwd2(WP(17), X0(17), X1(17), fA0, fA1,  fA0, fA1); ST(fA, 12);
    FLUSH(5);
    // ---- phase 6: {18,19,20}  (fC=f16, fA=f17; 18<-16, 19<-17, 20<-18) ----
    joint_fwd2(WP(18), X0(18), X1(18), fC0, fC1,  fB0, fB1); ST(fB, 0);
    joint_fwd2(WP(19), X0(19), X1(19), fA0, fA1,  fA0, fA1); ST(fA, 6);
    joint_fwd2(WP(20), X0(20), X1(20), fB0, fB1,  fB0, fB1); ST(fB, 12);
    FLUSH(6);
    // ---- phase 7: {21,22,23}  (fA=f19, fB=f20; 21<-19, 22<-20, 23<-21) ----
    joint_fwd2(WP(21), X0(21), X1(21), fA0, fA1,  fC0, fC1); ST(fC, 0);
    joint_fwd2(WP(22), X0(22), X1(22), fB0, fB1,  fB0, fB1); ST(fB, 6);
    joint_fwd2(WP(23), X0(23), X1(23), fC0, fC1,  fA0, fA1); ST(fA, 12);
    FLUSH(7);

#undef X0
#undef X1
#undef WP
#undef ST
#undef FLUSH
}

extern "C" void kernel_launch(void* const* d_in, const int* in_sizes, int n_in,
                              void* d_out, int out_size) {
    const float* x  = (const float*)d_in[0];
    const float* W1 = (const float*)d_in[1];
    const float* b1 = (const float*)d_in[2];
    const float* W2 = (const float*)d_in[3];
    const float* b2 = (const float*)d_in[4];
    float* out = (float*)d_out;

    int B = in_sizes[0] / 24;
    int warps  = (B + 127) / 128;          // each warp covers 128 elements
    int blocks = (warps + WPB - 1) / WPB;

    cudaFuncSetAttribute(StructureEncoder1D_kernel,
                         cudaFuncAttributeMaxDynamicSharedMemorySize, SMEM_BYTES);
    StructureEncoder1D_kernel<<<blocks, WPB * 32, SMEM_BYTES>>>(x, W1, b1, W2, b2, out, B);
}

// round 8
// speedup vs baseline: 1.0554x; 1.0554x over previous
#include <cuda_runtime.h>
#include <cstdint>

typedef unsigned long long ull;

// ---------- packed f32x2 helpers (sm_103a) ----------
__device__ __forceinline__ ull pack2(float a, float b) {
    ull r; asm("mov.b64 %0, {%1, %2};" : "=l"(r) : "f"(a), "f"(b)); return r;
}
__device__ __forceinline__ void unpack2(ull v, float& a, float& b) {
    asm("mov.b64 {%0, %1}, %2;" : "=f"(a), "=f"(b) : "l"(v));
}
__device__ __forceinline__ ull ffma2(ull a, ull b, ull c) {
    ull d; asm("fma.rn.f32x2 %0, %1, %2, %3;" : "=l"(d) : "l"(a), "l"(b), "l"(c)); return d;
}
__device__ __forceinline__ ull relu2(ull v) {
    float a, b; unpack2(v, a, b);
    return pack2(fmaxf(a, 0.f), fmaxf(b, 0.f));
}

#define NJ 24
#define JW 104          // ull per joint: 13 rows x 8 (7 dup weights + dup bias)
#define WPB 8           // warps per block
#define XPAD 25         // x slab row stride in floats (odd -> conflict-free scalar LDS)
#define TPAD 18         // out tile row stride in floats (even -> aligned float2)
#define XSLAB_BYTES (128 * XPAD * 4)            // 12800
#define TILE_BYTES  (128 * TPAD * 4)            // 9216
#define FS_BYTES    (12 * 32 * 8)               // 3072
#define WARP_BYTES  (XSLAB_BYTES + TILE_BYTES + FS_BYTES)   // 25088
#define SW_BYTES (NJ * JW * 8)                  // 19968
#define SMEM_BYTES (SW_BYTES + WPB * WARP_BYTES)            // 220672

// ---- joint forward for BOTH packs, sharing weight registers ----
__device__ __forceinline__ void joint_fwd2(const ull* wp, ull xp0, ull xp1,
                                           const ull* pf0, const ull* pf1,
                                           ull* fo0, ull* fo1) {
    ull h0[7], h1[7];
#pragma unroll
    for (int o = 0; o < 7; ++o) {
        const ulonglong2* r = reinterpret_cast<const ulonglong2*>(wp + o * 8);
        ulonglong2 q0 = r[0], q1 = r[1], q2 = r[2], q3 = r[3];
        ull a0 = ffma2(q0.x, xp0, q3.y);
        ull a1 = ffma2(q0.x, xp1, q3.y);
        a0 = ffma2(q0.y, pf0[0], a0);  a1 = ffma2(q0.y, pf1[0], a1);
        a0 = ffma2(q1.x, pf0[1], a0);  a1 = ffma2(q1.x, pf1[1], a1);
        a0 = ffma2(q1.y, pf0[2], a0);  a1 = ffma2(q1.y, pf1[2], a1);
        a0 = ffma2(q2.x, pf0[3], a0);  a1 = ffma2(q2.x, pf1[3], a1);
        a0 = ffma2(q2.y, pf0[4], a0);  a1 = ffma2(q2.y, pf1[4], a1);
        a0 = ffma2(q3.x, pf0[5], a0);  a1 = ffma2(q3.x, pf1[5], a1);
        h0[o] = relu2(a0);  h1[o] = relu2(a1);
    }
#pragma unroll
    for (int o = 0; o < 6; ++o) {
        const ulonglong2* r = reinterpret_cast<const ulonglong2*>(wp + 56 + o * 8);
        ulonglong2 q0 = r[0], q1 = r[1], q2 = r[2], q3 = r[3];
        ull a0 = ffma2(q0.x, h0[0], q3.y);
        ull a1 = ffma2(q0.x, h1[0], q3.y);
        a0 = ffma2(q0.y, h0[1], a0);  a1 = ffma2(q0.y, h1[1], a1);
        a0 = ffma2(q1.x, h0[2], a0);  a1 = ffma2(q1.x, h1[2], a1);
        a0 = ffma2(q1.y, h0[3], a0);  a1 = ffma2(q1.y, h1[3], a1);
        a0 = ffma2(q2.x, h0[4], a0);  a1 = ffma2(q2.x, h1[4], a1);
        a0 = ffma2(q2.y, h0[5], a0);  a1 = ffma2(q2.y, h1[5], a1);
        a0 = ffma2(q3.x, h0[6], a0);  a1 = ffma2(q3.x, h1[6], a1);
        fo0[o] = relu2(a0);  fo1[o] = relu2(a1);
    }
}

// parent features taken from the fs smem slab
__device__ __forceinline__ void joint_fwd2_s(const ull* wp, ull xp0, ull xp1,
                                             const ull* fs, int lane,
                                             ull* fo0, ull* fo1) {
    ull pf0[6], pf1[6];
#pragma unroll
    for (int s = 0; s < 6; ++s) {
        pf0[s] = fs[s * 32 + lane];
        pf1[s] = fs[(6 + s) * 32 + lane];
    }
    joint_fwd2(wp, xp0, xp1, pf0, pf1, fo0, fo1);
}

__device__ __forceinline__ void root_fwd2(const ull* wp, ull xp0, ull xp1,
                                          ull* fo0, ull* fo1) {
    ull h0[7], h1[7];
#pragma unroll
    for (int o = 0; o < 7; ++o) {
        ull w0 = wp[o * 8];
        ull bb = wp[o * 8 + 7];
        h0[o] = relu2(ffma2(w0, xp0, bb));
        h1[o] = relu2(ffma2(w0, xp1, bb));
    }
#pragma unroll
    for (int o = 0; o < 6; ++o) {
        const ulonglong2* r = reinterpret_cast<const ulonglong2*>(wp + 56 + o * 8);
        ulonglong2 q0 = r[0], q1 = r[1], q2 = r[2], q3 = r[3];
        ull a0 = ffma2(q0.x, h0[0], q3.y);
        ull a1 = ffma2(q0.x, h1[0], q3.y);
        a0 = ffma2(q0.y, h0[1], a0);  a1 = ffma2(q0.y, h1[1], a1);
        a0 = ffma2(q1.x, h0[2], a0);  a1 = ffma2(q1.x, h1[2], a1);
        a0 = ffma2(q1.y, h0[3], a0);  a1 = ffma2(q1.y, h1[3], a1);
        a0 = ffma2(q2.x, h0[4], a0);  a1 = ffma2(q2.x, h1[4], a1);
        a0 = ffma2(q2.y, h0[5], a0);  a1 = ffma2(q2.y, h1[5], a1);
        a0 = ffma2(q3.x, h0[6], a0);  a1 = ffma2(q3.x, h1[6], a1);
        fo0[o] = relu2(a0);  fo1[o] = relu2(a1);
    }
}

__device__ __forceinline__ void fsave(ull* fs, int lane, const ull* f0, const ull* f1) {
#pragma unroll
    for (int s = 0; s < 6; ++s) {
        fs[s * 32 + lane] = f0[s];
        fs[(6 + s) * 32 + lane] = f1[s];
    }
}

// store one pack's 6 values to two element rows in the tile
__device__ __forceinline__ void store6(const ull* f, float* ra, float* rb, int cb) {
    float a0,b0,a1,b1,a2,b2,a3,b3,a4,b4,a5,b5;
    unpack2(f[0], a0, b0); unpack2(f[1], a1, b1); unpack2(f[2], a2, b2);
    unpack2(f[3], a3, b3); unpack2(f[4], a4, b4); unpack2(f[5], a5, b5);
    ((float2*)(ra + cb))[0] = make_float2(a0, a1);
    ((float2*)(ra + cb))[1] = make_float2(a2, a3);
    ((float2*)(ra + cb))[2] = make_float2(a4, a5);
    ((float2*)(rb + cb))[0] = make_float2(b0, b1);
    ((float2*)(rb + cb))[1] = make_float2(b2, b3);
    ((float2*)(rb + cb))[2] = make_float2(b4, b5);
}

__global__ void __launch_bounds__(WPB * 32)
StructureEncoder1D_kernel(const float* __restrict__ x,
                          const float* __restrict__ W1,
                          const float* __restrict__ b1,
                          const float* __restrict__ W2,
                          const float* __restrict__ b2,
                          float* __restrict__ out, int B) {
    extern __shared__ __align__(16) char dynsmem[];
    ull* sw = reinterpret_cast<ull*>(dynsmem);

    // ---- cooperative weight fill: each ull = one weight duplicated ----
    for (int i = threadIdx.x; i < NJ * JW; i += blockDim.x) {
        int j = i / JW, r = i % JW, row = r >> 3, c = r & 7;
        float v;
        if (row < 7) {
            v = (c < 7) ? W1[j * 49 + row * 7 + c] : b1[j * 7 + row];
        } else {
            int rr = row - 7;
            v = (c < 7) ? W2[j * 42 + rr * 7 + c] : b2[j * 6 + rr];
        }
        ull u = (ull)__float_as_uint(v);
        sw[i] = u | (u << 32);
    }
    __syncthreads();

    const int lane   = threadIdx.x & 31;
    const int warpId = threadIdx.x >> 5;
    const int warpBase = (blockIdx.x * WPB + warpId) * 128;   // 128 elems/warp
    if (warpBase >= B) return;

    char* wb = dynsmem + SW_BYTES + warpId * WARP_BYTES;
    float* xslab = reinterpret_cast<float*>(wb);
    float* tile  = reinterpret_cast<float*>(wb + XSLAB_BYTES);
    ull*   fs    = reinterpret_cast<ull*>(wb + XSLAB_BYTES + TILE_BYTES);

    // ---- stage x: coalesced LDG.128 -> xslab (row stride 25 floats) ----
    {
        const float4* xin = reinterpret_cast<const float4*>(x);
#pragma unroll
        for (int k = 0; k < 24; ++k) {
            int i = k * 32 + lane;               // [0,768): 128 rows x 6 float4
            int r = i / 6, c = i % 6;
            float4 v = make_float4(0.f, 0.f, 0.f, 0.f);
            if (warpBase + r < B) v = xin[(size_t)(warpBase + r) * 6 + c];
            float* d = xslab + r * XPAD + c * 4;
            d[0] = v.x; d[1] = v.y; d[2] = v.z; d[3] = v.w;
        }
    }
    __syncwarp();

    float* ra = tile + lane * TPAD;
    float* rb = tile + (lane + 32) * TPAD;
    float* rc = tile + (lane + 64) * TPAD;
    float* rd = tile + (lane + 96) * TPAD;

    ull A0[6], A1[6], B0[6], B1[6];

#define X0(J) pack2(xslab[lane * XPAD + (J)], xslab[(lane + 32) * XPAD + (J)])
#define X1(J) pack2(xslab[(lane + 64) * XPAD + (J)], xslab[(lane + 96) * XPAD + (J)])
#define WP(J) (sw + (J) * JW)
#define ST(F, J) do { store6(F##0, ra, rb, ((J) % 3) * 6);                     \
                      store6(F##1, rc, rd, ((J) % 3) * 6); } while (0)
// joint whose parent AND result both live in fs (branch-point chain 0->3->6->9, and 14)
#define JNT_SS(J) do {                                                         \
        ull t0[6], t1[6];                                                      \
        joint_fwd2_s(WP(J), X0(J), X1(J), fs, lane, t0, t1);                   \
        ST(t, J); fsave(fs, lane, t0, t1);                                     \
    } while (0)

    // flush tile (18 cols) to out cols [G*18, G*18+18)
#define FLUSH(G) do {                                                          \
        __syncwarp();                                                          \
        _Pragma("unroll")                                                      \
        for (int k = 0; k < 36; ++k) {                                         \
            int i = k * 32 + lane;               /* [0,1152): 128 rows x 9 */  \
            int r = i / 9, c = i % 9;                                          \
            if (warpBase + r < B) {                                            \
                float2 v = *reinterpret_cast<const float2*>(                   \
                    tile + r * TPAD + c * 2);                                  \
                *reinterpret_cast<float2*>(                                    \
                    out + (size_t)(warpBase + r) * 144 + (G) * 18 + c * 2) = v;\
            }                                                                  \
        }                                                                      \
        __syncwarp();                                                          \
    } while (0)

    // ---- phase 0: {0,1,2} ----
    root_fwd2(WP(0), X0(0), X1(0), A0, A1);            // A = f0
    ST(A, 0); fsave(fs, lane, A0, A1);                 // S = f0
    joint_fwd2(WP(1), X0(1), X1(1), A0, A1, B0, B1);   // B = f1
    ST(B, 1);
    joint_fwd2(WP(2), X0(2), X1(2), A0, A1, A0, A1);   // A = f2
    ST(A, 2);
    FLUSH(0);

    // ---- phase 1: {3,4,5}  (S=f0, B=f1, A=f2) ----
    joint_fwd2(WP(4), X0(4), X1(4), B0, B1, B0, B1); ST(B, 4);  // B = f4
    joint_fwd2(WP(5), X0(5), X1(5), A0, A1, A0, A1); ST(A, 5);  // A = f5
    JNT_SS(3);                                                   // S = f3
    FLUSH(1);

    // ---- phase 2: {6,7,8}  (S=f3, B=f4, A=f5) ----
    joint_fwd2(WP(7), X0(7), X1(7), B0, B1, B0, B1); ST(B, 7);  // B = f7
    joint_fwd2(WP(8), X0(8), X1(8), A0, A1, A0, A1); ST(A, 8);  // A = f8
    JNT_SS(6);                                                   // S = f6
    FLUSH(2);

    // ---- phase 3: {9,10,11}  (S=f6, B=f7, A=f8) ----
    joint_fwd2(WP(10), X0(10), X1(10), B0, B1, B0, B1); ST(B, 10);
    joint_fwd2(WP(11), X0(11), X1(11), A0, A1, A0, A1); ST(A, 11);
    JNT_SS(9);                                                   // S = f9
    FLUSH(3);

    // ---- phase 4: {12,13,14}  (S=f9) ----
    joint_fwd2_s(WP(12), X0(12), X1(12), fs, lane, A0, A1); ST(A, 12); // A = f12
    joint_fwd2_s(WP(13), X0(13), X1(13), fs, lane, B0, B1); ST(B, 13); // B = f13
    JNT_SS(14);                                                  // S = f14
    FLUSH(4);

    // ---- phase 5: {15,16,17}  (A=f12, B=f13, S=f14) ----
    joint_fwd2(WP(15), X0(15), X1(15), A0, A1, A0, A1); ST(A, 15); // A dead (15 terminal)
    joint_fwd2(WP(16), X0(16), X1(16), B0, B1, B0, B1); ST(B, 16); // B = f16
    joint_fwd2_s(WP(17), X0(17), X1(17), fs, lane, A0, A1); ST(A, 17); // A = f17
    FLUSH(5);

    // ---- phase 6: {18,19,20}  (B=f16, A=f17) ----
    joint_fwd2(WP(18), X0(18), X1(18), B0, B1, B0, B1); ST(B, 18); // B = f18
    joint_fwd2(WP(19), X0(19), X1(19), A0, A1, A0, A1); ST(A, 19); // A = f19
    joint_fwd2(WP(20), X0(20), X1(20), B0, B1, B0, B1); ST(B, 20); // B = f20
    FLUSH(6);

    // ---- phase 7: {21,22,23}  (A=f19, B=f20) ----
    joint_fwd2(WP(21), X0(21), X1(21), A0, A1, A0, A1); ST(A, 21); // A = f21
    joint_fwd2(WP(22), X0(22), X1(22), B0, B1, B0, B1); ST(B, 22);
    joint_fwd2(WP(23), X0(23), X1(23), A0, A1, A0, A1); ST(A, 23);
    FLUSH(7);

#undef X0
#undef X1
#undef WP
#undef ST
#undef JNT_SS
#undef FLUSH
}

extern "C" void kernel_launch(void* const* d_in, const int* in_sizes, int n_in,
                              void* d_out, int out_size) {
    const float* x  = (const float*)d_in[0];
    const float* W1 = (const float*)d_in[1];
    const float* b1 = (const float*)d_in[2];
    const float* W2 = (const float*)d_in[3];
    const float* b2 = (const float*)d_in[4];
    float* out = (float*)d_out;

    int B = in_sizes[0] / 24;
    int warps  = (B + 127) / 128;          // each warp covers 128 elements
    int blocks = (warps + WPB - 1) / WPB;

    cudaFuncSetAttribute(StructureEncoder1D_kernel,
                         cudaFuncAttributeMaxDynamicSharedMemorySize, SMEM_BYTES);
    StructureEncoder1D_kernel<<<blocks, WPB * 32, SMEM_BYTES>>>(x, W1, b1, W2, b2, out, B);
}

// round 9
// speedup vs baseline: 4.0016x; 3.7915x over previous
#include <cuda_runtime.h>
#include <cstdint>

typedef unsigned long long ull;

// ---------- packed f32x2 helpers (sm_103a) ----------
__device__ __forceinline__ ull pack2(float a, float b) {
    ull r; asm("mov.b64 %0, {%1, %2};" : "=l"(r) : "f"(a), "f"(b)); return r;
}
__device__ __forceinline__ void unpack2(ull v, float& a, float& b) {
    asm("mov.b64 {%0, %1}, %2;" : "=f"(a), "=f"(b) : "l"(v));
}
__device__ __forceinline__ ull ffma2(ull a, ull b, ull c) {
    ull d; asm("fma.rn.f32x2 %0, %1, %2, %3;" : "=l"(d) : "l"(a), "l"(b), "l"(c)); return d;
}
__device__ __forceinline__ ull relu2(ull v) {
    float a, b; unpack2(v, a, b);
    return pack2(fmaxf(a, 0.f), fmaxf(b, 0.f));
}
#define DUP(f) pack2((f), (f))   // 1 ALU op: duplicate scalar weight into both halves

#define NJ 24
#define JWF 104         // floats per joint: 13 rows x 8 (7 weights + bias), NON-dup
#define WPB 8           // warps per block
#define TPAD 74         // tile row stride in floats (even -> aligned float2 ops)
#define TILE_FLOATS (64 * TPAD)                  // 18944 B
#define XS_ULL (24 * 32)                         // packed-x per warp: 6144 B
#define SW_BYTES (NJ * JWF * 4)                  // 9984
#define WARP_BYTES (XS_ULL * 8 + TILE_FLOATS * 4)          // 25088
#define SMEM_BYTES (SW_BYTES + WPB * WARP_BYTES)           // 210688

// ---- full joint: 7x7 layer1 + 6x7 layer2, non-dup weights (float4 view) ----
__device__ __forceinline__ void joint_fwd(const float4* wp, ull xp,
                                          const ull* pf, ull* fo) {
    ull h[7];
#pragma unroll
    for (int o = 0; o < 7; ++o) {
        float4 wa = wp[o * 2], wb = wp[o * 2 + 1];   // w0..w3 | w4,w5,w6,bias
        ull acc = ffma2(DUP(wa.x), xp, DUP(wb.w));
        acc = ffma2(DUP(wa.y), pf[0], acc);
        acc = ffma2(DUP(wa.z), pf[1], acc);
        acc = ffma2(DUP(wa.w), pf[2], acc);
        acc = ffma2(DUP(wb.x), pf[3], acc);
        acc = ffma2(DUP(wb.y), pf[4], acc);
        acc = ffma2(DUP(wb.z), pf[5], acc);
        h[o] = relu2(acc);
    }
#pragma unroll
    for (int o = 0; o < 6; ++o) {
        float4 wa = wp[14 + o * 2], wb = wp[14 + o * 2 + 1];
        ull acc = ffma2(DUP(wa.x), h[0], DUP(wb.w));
        acc = ffma2(DUP(wa.y), h[1], acc);
        acc = ffma2(DUP(wa.z), h[2], acc);
        acc = ffma2(DUP(wa.w), h[3], acc);
        acc = ffma2(DUP(wb.x), h[4], acc);
        acc = ffma2(DUP(wb.y), h[5], acc);
        acc = ffma2(DUP(wb.z), h[6], acc);
        fo[o] = relu2(acc);
    }
}

// root: parent features are zero
__device__ __forceinline__ void root_fwd(const float4* wp, ull xp, ull* fo) {
    ull h[7];
#pragma unroll
    for (int o = 0; o < 7; ++o) {
        float4 wa = wp[o * 2], wb = wp[o * 2 + 1];
        h[o] = relu2(ffma2(DUP(wa.x), xp, DUP(wb.w)));
    }
#pragma unroll
    for (int o = 0; o < 6; ++o) {
        float4 wa = wp[14 + o * 2], wb = wp[14 + o * 2 + 1];
        ull acc = ffma2(DUP(wa.x), h[0], DUP(wb.w));
        acc = ffma2(DUP(wa.y), h[1], acc);
        acc = ffma2(DUP(wa.z), h[2], acc);
        acc = ffma2(DUP(wa.w), h[3], acc);
        acc = ffma2(DUP(wb.x), h[4], acc);
        acc = ffma2(DUP(wb.y), h[5], acc);
        acc = ffma2(DUP(wb.z), h[6], acc);
        fo[o] = relu2(acc);
    }
}

// store 6 packed values: lows -> row ra, highs -> row rb (aligned float2)
__device__ __forceinline__ void store6(const ull* f, float* ra, float* rb, int cb) {
    float a0,b0,a1,b1,a2,b2,a3,b3,a4,b4,a5,b5;
    unpack2(f[0], a0, b0); unpack2(f[1], a1, b1); unpack2(f[2], a2, b2);
    unpack2(f[3], a3, b3); unpack2(f[4], a4, b4); unpack2(f[5], a5, b5);
    ((float2*)(ra + cb))[0] = make_float2(a0, a1);
    ((float2*)(ra + cb))[1] = make_float2(a2, a3);
    ((float2*)(ra + cb))[2] = make_float2(a4, a5);
    ((float2*)(rb + cb))[0] = make_float2(b0, b1);
    ((float2*)(rb + cb))[1] = make_float2(b2, b3);
    ((float2*)(rb + cb))[2] = make_float2(b4, b5);
}

__global__ void __launch_bounds__(WPB * 32)
StructureEncoder1D_kernel(const float* __restrict__ x,
                          const float* __restrict__ W1,
                          const float* __restrict__ b1,
                          const float* __restrict__ W2,
                          const float* __restrict__ b2,
                          float* __restrict__ out, int B) {
    extern __shared__ __align__(16) char dynsmem[];
    float* sw    = reinterpret_cast<float*>(dynsmem);                // non-dup weights
    char*  wbase = dynsmem + SW_BYTES;

    // ---- cooperative weight fill (plain floats, rows of 8) ----
    for (int i = threadIdx.x; i < NJ * JWF; i += blockDim.x) {
        int j = i / JWF, r = i % JWF, row = r >> 3, c = r & 7;
        float v;
        if (row < 7) {
            v = (c < 7) ? W1[j * 49 + row * 7 + c] : b1[j * 7 + row];
        } else {
            int rr = row - 7;
            v = (c < 7) ? W2[j * 42 + rr * 7 + c] : b2[j * 6 + rr];
        }
        sw[i] = v;
    }
    __syncthreads();

    const int lane   = threadIdx.x & 31;
    const int warpId = threadIdx.x >> 5;
    const int warpBase = (blockIdx.x * WPB + warpId) * 64;
    if (warpBase >= B) return;

    char* wb = wbase + warpId * WARP_BYTES;
    ull*   xs   = reinterpret_cast<ull*>(wb);
    float* tile = reinterpret_cast<float*>(wb + XS_ULL * 8);

    // ---- stage x: coalesced LDG.128 -> tile region (row stride 25 floats) ----
    {
        const float4* xin = reinterpret_cast<const float4*>(x);
#pragma unroll
        for (int k = 0; k < 12; ++k) {
            int i = k * 32 + lane;               // [0,384): 64 rows x 6 float4
            int r = i / 6, c = i % 6;
            float4 v = make_float4(0.f, 0.f, 0.f, 0.f);
            if (warpBase + r < B) v = xin[(size_t)(warpBase + r) * 6 + c];
            float* d = tile + r * 25 + c * 4;
            d[0] = v.x; d[1] = v.y; d[2] = v.z; d[3] = v.w;
        }
    }
    __syncwarp();

    // ---- build packed-x in xs: xs[j*32+lane] = {x[e0][j], x[e1][j]} ----
#pragma unroll
    for (int j = 0; j < 24; ++j) {
        float a = tile[lane * 25 + j];
        float b = tile[(lane + 32) * 25 + j];
        xs[j * 32 + lane] = pack2(a, b);
    }
    __syncwarp();

    float* ta = tile + lane * TPAD;          // even offset -> aligned
    float* tb = tile + (lane + 32) * TPAD;

    ull f0[6], f9[6], cur[6];

#define XP(J) (xs[(J) * 32 + lane])
#define WP(J) (reinterpret_cast<const float4*>(sw) + (J) * 26)
#define ST(F, CB) store6(F, ta, tb, CB)

#define FLUSH(H) do {                                                          \
        __syncwarp();                                                          \
        _Pragma("unroll")                                                      \
        for (int k = 0; k < 36; ++k) {                                         \
            int i = k * 32 + lane;               /* [0,1152): 64 rows x 18 */  \
            int r = i / 18, c = i % 18;                                        \
            if (warpBase + r < B) {                                            \
                const float2* s = reinterpret_cast<const float2*>(             \
                    tile + r * TPAD + c * 4);                                  \
                float2 lo = s[0], hi = s[1];                                   \
                *reinterpret_cast<float4*>(                                    \
                    out + (size_t)(warpBase + r) * 144 + (H) * 72 + c * 4) =   \
                    make_float4(lo.x, lo.y, hi.x, hi.y);                       \
            }                                                                  \
        }                                                                      \
        __syncwarp();                                                          \
    } while (0)

    // ---- first half: DFS over joints 0..11 (cols = j*6) ----
    root_fwd (WP(0),  XP(0),        f0);  ST(f0,  0 * 6);
    joint_fwd(WP(1),  XP(1),  f0,  cur);  ST(cur, 1 * 6);
    joint_fwd(WP(4),  XP(4),  cur, cur);  ST(cur, 4 * 6);
    joint_fwd(WP(7),  XP(7),  cur, cur);  ST(cur, 7 * 6);
    joint_fwd(WP(10), XP(10), cur, cur);  ST(cur, 10 * 6);
    joint_fwd(WP(2),  XP(2),  f0,  cur);  ST(cur, 2 * 6);
    joint_fwd(WP(5),  XP(5),  cur, cur);  ST(cur, 5 * 6);
    joint_fwd(WP(8),  XP(8),  cur, cur);  ST(cur, 8 * 6);
    joint_fwd(WP(11), XP(11), cur, cur);  ST(cur, 11 * 6);
    joint_fwd(WP(3),  XP(3),  f0,  cur);  ST(cur, 3 * 6);
    joint_fwd(WP(6),  XP(6),  cur, cur);  ST(cur, 6 * 6);
    joint_fwd(WP(9),  XP(9),  cur, f9);   ST(f9,  9 * 6);

    FLUSH(0);

    // ---- second half: joints 12..23 (cols = (j-12)*6) ----
    joint_fwd(WP(12), XP(12), f9,  cur);  ST(cur, 0 * 6);
    joint_fwd(WP(15), XP(15), cur, cur);  ST(cur, 3 * 6);
    joint_fwd(WP(13), XP(13), f9,  cur);  ST(cur, 1 * 6);
    joint_fwd(WP(16), XP(16), cur, cur);  ST(cur, 4 * 6);
    joint_fwd(WP(18), XP(18), cur, cur);  ST(cur, 6 * 6);
    joint_fwd(WP(20), XP(20), cur, cur);  ST(cur, 8 * 6);
    joint_fwd(WP(22), XP(22), cur, cur);  ST(cur, 10 * 6);
    joint_fwd(WP(14), XP(14), f9,  cur);  ST(cur, 2 * 6);
    joint_fwd(WP(17), XP(17), cur, cur);  ST(cur, 5 * 6);
    joint_fwd(WP(19), XP(19), cur, cur);  ST(cur, 7 * 6);
    joint_fwd(WP(21), XP(21), cur, cur);  ST(cur, 9 * 6);
    joint_fwd(WP(23), XP(23), cur, cur);  ST(cur, 11 * 6);

    FLUSH(1);

#undef XP
#undef WP
#undef ST
#undef FLUSH
}

extern "C" void kernel_launch(void* const* d_in, const int* in_sizes, int n_in,
                              void* d_out, int out_size) {
    const float* x  = (const float*)d_in[0];
    const float* W1 = (const float*)d_in[1];
    const float* b1 = (const float*)d_in[2];
    const float* W2 = (const float*)d_in[3];
    const float* b2 = (const float*)d_in[4];
    float* out = (float*)d_out;

    int B = in_sizes[0] / 24;
    int warps  = (B + 63) / 64;
    int blocks = (warps + WPB - 1) / WPB;

    cudaFuncSetAttribute(StructureEncoder1D_kernel,
                         cudaFuncAttributeMaxDynamicSharedMemorySize, SMEM_BYTES);
    StructureEncoder1D_kernel<<<blocks, WPB * 32, SMEM_BYTES>>>(x, W1, b1, W2, b2, out, B);
}

// round 10
// speedup vs baseline: 4.2359x; 1.0585x over previous
#include <cuda_runtime.h>
#include <cstdint>

typedef unsigned long long ull;

// ---------- packed f32x2 helpers (sm_103a) ----------
__device__ __forceinline__ ull pack2(float a, float b) {
    ull r; asm("mov.b64 %0, {%1, %2};" : "=l"(r) : "f"(a), "f"(b)); return r;
}
__device__ __forceinline__ void unpack2(ull v, float& a, float& b) {
    asm("mov.b64 {%0, %1}, %2;" : "=f"(a), "=f"(b) : "l"(v));
}
__device__ __forceinline__ ull ffma2(ull a, ull b, ull c) {
    ull d; asm("fma.rn.f32x2 %0, %1, %2, %3;" : "=l"(d) : "l"(a), "l"(b), "l"(c)); return d;
}
__device__ __forceinline__ ull relu2(ull v) {
    float a, b; unpack2(v, a, b);
    return pack2(fmaxf(a, 0.f), fmaxf(b, 0.f));
}
#define DUP(f) pack2((f), (f))   // 1 ALU op: duplicate scalar weight into both halves

#define NJ 24
#define JWF 104         // floats per joint: 13 rows x 8 (7 weights + bias), NON-dup
#define WPB 12          // warps per block
#define TPAD 38         // quarter-tile row stride in floats (even; stride-6 banks conflict-free)
#define TILE_FLOATS (64 * TPAD)                  // 9728 B
#define XS_ULL (24 * 32)                         // packed-x per warp: 6144 B
#define SW_BYTES (NJ * JWF * 4)                  // 9984
#define WARP_BYTES (XS_ULL * 8 + TILE_FLOATS * 4)          // 15872
#define SMEM_BYTES (SW_BYTES + WPB * WARP_BYTES)           // 200448

// ---- full joint: 7x7 layer1 + 6x7 layer2, non-dup weights (float4 view) ----
__device__ __forceinline__ void joint_fwd(const float4* wp, ull xp,
                                          const ull* pf, ull* fo) {
    ull h[7];
#pragma unroll
    for (int o = 0; o < 7; ++o) {
        float4 wa = wp[o * 2], wb = wp[o * 2 + 1];   // w0..w3 | w4,w5,w6,bias
        ull acc = ffma2(DUP(wa.x), xp, DUP(wb.w));
        acc = ffma2(DUP(wa.y), pf[0], acc);
        acc = ffma2(DUP(wa.z), pf[1], acc);
        acc = ffma2(DUP(wa.w), pf[2], acc);
        acc = ffma2(DUP(wb.x), pf[3], acc);
        acc = ffma2(DUP(wb.y), pf[4], acc);
        acc = ffma2(DUP(wb.z), pf[5], acc);
        h[o] = relu2(acc);
    }
#pragma unroll
    for (int o = 0; o < 6; ++o) {
        float4 wa = wp[14 + o * 2], wb = wp[14 + o * 2 + 1];
        ull acc = ffma2(DUP(wa.x), h[0], DUP(wb.w));
        acc = ffma2(DUP(wa.y), h[1], acc);
        acc = ffma2(DUP(wa.z), h[2], acc);
        acc = ffma2(DUP(wa.w), h[3], acc);
        acc = ffma2(DUP(wb.x), h[4], acc);
        acc = ffma2(DUP(wb.y), h[5], acc);
        acc = ffma2(DUP(wb.z), h[6], acc);
        fo[o] = relu2(acc);
    }
}

// root: parent features are zero
__device__ __forceinline__ void root_fwd(const float4* wp, ull xp, ull* fo) {
    ull h[7];
#pragma unroll
    for (int o = 0; o < 7; ++o) {
        float4 wa = wp[o * 2], wb = wp[o * 2 + 1];
        h[o] = relu2(ffma2(DUP(wa.x), xp, DUP(wb.w)));
    }
#pragma unroll
    for (int o = 0; o < 6; ++o) {
        float4 wa = wp[14 + o * 2], wb = wp[14 + o * 2 + 1];
        ull acc = ffma2(DUP(wa.x), h[0], DUP(wb.w));
        acc = ffma2(DUP(wa.y), h[1], acc);
        acc = ffma2(DUP(wa.z), h[2], acc);
        acc = ffma2(DUP(wa.w), h[3], acc);
        acc = ffma2(DUP(wb.x), h[4], acc);
        acc = ffma2(DUP(wb.y), h[5], acc);
        acc = ffma2(DUP(wb.z), h[6], acc);
        fo[o] = relu2(acc);
    }
}

// store 6 packed values: lows -> row ra, highs -> row rb (aligned float2)
__device__ __forceinline__ void store6(const ull* f, float* ra, float* rb, int cb) {
    float a0,b0,a1,b1,a2,b2,a3,b3,a4,b4,a5,b5;
    unpack2(f[0], a0, b0); unpack2(f[1], a1, b1); unpack2(f[2], a2, b2);
    unpack2(f[3], a3, b3); unpack2(f[4], a4, b4); unpack2(f[5], a5, b5);
    ((float2*)(ra + cb))[0] = make_float2(a0, a1);
    ((float2*)(ra + cb))[1] = make_float2(a2, a3);
    ((float2*)(ra + cb))[2] = make_float2(a4, a5);
    ((float2*)(rb + cb))[0] = make_float2(b0, b1);
    ((float2*)(rb + cb))[1] = make_float2(b2, b3);
    ((float2*)(rb + cb))[2] = make_float2(b4, b5);
}

__global__ void __launch_bounds__(WPB * 32)
StructureEncoder1D_kernel(const float* __restrict__ x,
                          const float* __restrict__ W1,
                          const float* __restrict__ b1,
                          const float* __restrict__ W2,
                          const float* __restrict__ b2,
                          float* __restrict__ out, int B) {
    extern __shared__ __align__(16) char dynsmem[];
    float* sw    = reinterpret_cast<float*>(dynsmem);                // non-dup weights
    char*  wbase = dynsmem + SW_BYTES;

    // ---- cooperative weight fill (plain floats, rows of 8) ----
    for (int i = threadIdx.x; i < NJ * JWF; i += blockDim.x) {
        int j = i / JWF, r = i % JWF, row = r >> 3, c = r & 7;
        float v;
        if (row < 7) {
            v = (c < 7) ? W1[j * 49 + row * 7 + c] : b1[j * 7 + row];
        } else {
            int rr = row - 7;
            v = (c < 7) ? W2[j * 42 + rr * 7 + c] : b2[j * 6 + rr];
        }
        sw[i] = v;
    }
    __syncthreads();

    const int lane   = threadIdx.x & 31;
    const int warpId = threadIdx.x >> 5;
    const int warpBase = (blockIdx.x * WPB + warpId) * 64;
    if (warpBase >= B) return;

    char* wb = wbase + warpId * WARP_BYTES;
    ull*   xs   = reinterpret_cast<ull*>(wb);
    float* tile = reinterpret_cast<float*>(wb + XS_ULL * 8);

    // ---- stage x: coalesced LDG.128 -> tile region (row stride 25 floats) ----
    {
        const float4* xin = reinterpret_cast<const float4*>(x);
#pragma unroll
        for (int k = 0; k < 12; ++k) {
            int i = k * 32 + lane;               // [0,384): 64 rows x 6 float4
            int r = i / 6, c = i % 6;
            float4 v = make_float4(0.f, 0.f, 0.f, 0.f);
            if (warpBase + r < B) v = xin[(size_t)(warpBase + r) * 6 + c];
            float* d = tile + r * 25 + c * 4;
            d[0] = v.x; d[1] = v.y; d[2] = v.z; d[3] = v.w;
        }
    }
    __syncwarp();

    // ---- build packed-x in xs: xs[j*32+lane] = {x[e0][j], x[e1][j]} ----
#pragma unroll
    for (int j = 0; j < 24; ++j) {
        float a = tile[lane * 25 + j];
        float b = tile[(lane + 32) * 25 + j];
        xs[j * 32 + lane] = pack2(a, b);
    }
    __syncwarp();

    float* ta = tile + lane * TPAD;          // even offset -> aligned float2
    float* tb = tile + (lane + 32) * TPAD;

    ull fA[6], fB[6], fC[6];

#define XP(J) (xs[(J) * 32 + lane])
#define WP(J) (reinterpret_cast<const float4*>(sw) + (J) * 26)
#define ST(F, CB) store6(F, ta, tb, CB)

    // flush quarter tile: 64 rows x 36 cols -> out cols [G*36, G*36+36)
#define FLUSH(G) do {                                                          \
        __syncwarp();                                                          \
        _Pragma("unroll")                                                      \
        for (int k = 0; k < 18; ++k) {                                         \
            int i = k * 32 + lane;               /* [0,576): 64 rows x 9 f4 */ \
            int r = i / 9, c = i % 9;                                          \
            if (warpBase + r < B) {                                            \
                const float2* s = reinterpret_cast<const float2*>(             \
                    tile + r * TPAD + c * 4);                                  \
                float2 lo = s[0], hi = s[1];                                   \
                *reinterpret_cast<float4*>(                                    \
                    out + (size_t)(warpBase + r) * 144 + (G) * 36 + c * 4) =   \
                    make_float4(lo.x, lo.y, hi.x, hi.y);                       \
            }                                                                  \
        }                                                                      \
        __syncwarp();                                                          \
    } while (0)

    // ---- phase 0: joints {0..5}, local col = j*6 ----
    root_fwd (WP(0), XP(0),      fA);  ST(fA, 0 * 6);   // fA = f0
    joint_fwd(WP(1), XP(1), fA,  fB);  ST(fB, 1 * 6);   // fB = f1
    joint_fwd(WP(4), XP(4), fB,  fB);  ST(fB, 4 * 6);   // fB = f4
    joint_fwd(WP(2), XP(2), fA,  fC);  ST(fC, 2 * 6);   // fC = f2
    joint_fwd(WP(5), XP(5), fC,  fC);  ST(fC, 5 * 6);   // fC = f5
    joint_fwd(WP(3), XP(3), fA,  fA);  ST(fA, 3 * 6);   // fA = f3
    FLUSH(0);

    // ---- phase 1: joints {6..11}, local col = (j-6)*6  (fA=f3, fB=f4, fC=f5) ----
    joint_fwd(WP(6),  XP(6),  fA, fA); ST(fA, 0 * 6);   // fA = f6
    joint_fwd(WP(9),  XP(9),  fA, fA); ST(fA, 3 * 6);   // fA = f9
    joint_fwd(WP(7),  XP(7),  fB, fB); ST(fB, 1 * 6);   // fB = f7
    joint_fwd(WP(10), XP(10), fB, fB); ST(fB, 4 * 6);   // f10 (leaf)
    joint_fwd(WP(8),  XP(8),  fC, fC); ST(fC, 2 * 6);   // fC = f8
    joint_fwd(WP(11), XP(11), fC, fC); ST(fC, 5 * 6);   // f11 (leaf)
    FLUSH(1);

    // ---- phase 2: joints {12..17}, local col = (j-12)*6  (fA=f9) ----
    joint_fwd(WP(12), XP(12), fA, fB); ST(fB, 0 * 6);   // fB = f12
    joint_fwd(WP(15), XP(15), fB, fB); ST(fB, 3 * 6);   // f15 (leaf)
    joint_fwd(WP(13), XP(13), fA, fB); ST(fB, 1 * 6);   // fB = f13
    joint_fwd(WP(16), XP(16), fB, fB); ST(fB, 4 * 6);   // fB = f16 (keep)
    joint_fwd(WP(14), XP(14), fA, fC); ST(fC, 2 * 6);   // fC = f14
    joint_fwd(WP(17), XP(17), fC, fC); ST(fC, 5 * 6);   // fC = f17 (keep)
    FLUSH(2);

    // ---- phase 3: joints {18..23}, local col = (j-18)*6  (fB=f16, fC=f17) ----
    joint_fwd(WP(18), XP(18), fB, fB); ST(fB, 0 * 6);   // fB = f18
    joint_fwd(WP(20), XP(20), fB, fB); ST(fB, 2 * 6);   // fB = f20
    joint_fwd(WP(22), XP(22), fB, fB); ST(fB, 4 * 6);   // f22 (leaf)
    joint_fwd(WP(19), XP(19), fC, fC); ST(fC, 1 * 6);   // fC = f19
    joint_fwd(WP(21), XP(21), fC, fC); ST(fC, 3 * 6);   // fC = f21
    joint_fwd(WP(23), XP(23), fC, fC); ST(fC, 5 * 6);   // f23 (leaf)
    FLUSH(3);

#undef XP
#undef WP
#undef ST
#undef FLUSH
}

extern "C" void kernel_launch(void* const* d_in, const int* in_sizes, int n_in,
                              void* d_out, int out_size) {
    const float* x  = (const float*)d_in[0];
    const float* W1 = (const float*)d_in[1];
    const float* b1 = (const float*)d_in[2];
    const float* W2 = (const float*)d_in[3];
    const float* b2 = (const float*)d_in[4];
    float* out = (float*)d_out;

    int B = in_sizes[0] / 24;
    int warps  = (B + 63) / 64;
    int blocks = (warps + WPB - 1) / WPB;

    cudaFuncSetAttribute(StructureEncoder1D_kernel,
                         cudaFuncAttributeMaxDynamicSharedMemorySize, SMEM_BYTES);
    StructureEncoder1D_kernel<<<blocks, WPB * 32, SMEM_BYTES>>>(x, W1, b1, W2, b2, out, B);
}